// round 6
// baseline (speedup 1.0000x reference)
#include <cuda_runtime.h>
#include <cuda_bf16.h>
#include <cstdint>

#define Bb 32
#define Ll 512
#define Dd 512
#define Ss 8

// ---------------------------------------------------------------------------
// Device-global scratch
// ---------------------------------------------------------------------------
__device__ __nv_bfloat16 g_A2hi[(size_t)Bb * Ss * Ll * Dd];  // stage-1 out hi
__device__ __nv_bfloat16 g_A2lo[(size_t)Bb * Ss * Ll * Dd];  // stage-1 out lo
__device__ __nv_bfloat16 g_A1hi[(size_t)Bb * Ll * Dd];       // arg1 split
__device__ __nv_bfloat16 g_A1lo[(size_t)Bb * Ll * Dd];
__device__ __nv_bfloat16 g_B2hi[(size_t)Bb * Ll * Dd];       // arg2 split
__device__ __nv_bfloat16 g_B2lo[(size_t)Bb * Ll * Dd];
__device__ __nv_bfloat16 g_Mrhi[(size_t)Ss * Dd * Dd];       // Mr split
__device__ __nv_bfloat16 g_Mrlo[(size_t)Ss * Dd * Dd];
__device__ float g_P1[Bb * Ll * Ss];   // [b][i][k]
__device__ float g_Q1[Bb * Ll * Ss];
__device__ float g_P2t[Bb * Ss * Ll];  // [b][k][j]
__device__ float g_Q2t[Bb * Ss * Ll];

// ---------------------------------------------------------------------------
// Helpers
// ---------------------------------------------------------------------------
__device__ __forceinline__ uint32_t smem_u32(const void* p) {
    uint32_t a;
    asm("{ .reg .u64 t; cvta.to.shared.u64 t, %1; cvt.u32.u64 %0, t; }"
        : "=r"(a) : "l"(p));
    return a;
}
__device__ __forceinline__ void ldsm4(uint32_t* r, uint32_t a) {
    asm volatile("ldmatrix.sync.aligned.m8n8.x4.shared.b16 {%0,%1,%2,%3}, [%4];"
                 : "=r"(r[0]), "=r"(r[1]), "=r"(r[2]), "=r"(r[3]) : "r"(a) : "memory");
}
__device__ __forceinline__ void mma_bf16(float* c, const uint32_t* a, const uint32_t* b) {
    asm volatile("mma.sync.aligned.m16n8k16.row.col.f32.bf16.bf16.f32 "
                 "{%0,%1,%2,%3}, {%4,%5,%6,%7}, {%8,%9}, {%0,%1,%2,%3};"
                 : "+f"(c[0]), "+f"(c[1]), "+f"(c[2]), "+f"(c[3])
                 : "r"(a[0]), "r"(a[1]), "r"(a[2]), "r"(a[3]), "r"(b[0]), "r"(b[1]));
}
#define CP16(dst, src) \
    asm volatile("cp.async.cg.shared.global [%0], [%1], 16;" :: "r"(dst), "l"(src) : "memory")
#define CPCOMMIT() asm volatile("cp.async.commit_group;" ::: "memory")
#define CPWAIT1() asm volatile("cp.async.wait_group 1;" ::: "memory")
#define CPWAIT0() asm volatile("cp.async.wait_group 0;" ::: "memory")

__device__ __forceinline__ uint32_t pack_bf16x2(float a, float b) {
    uint32_t h;
    asm("cvt.rn.bf16x2.f32 %0, %1, %2;" : "=r"(h) : "f"(b), "f"(a));  // low=a
    return h;
}
__device__ __forceinline__ void split2(float a, float b, uint32_t& h, uint32_t& l) {
    h = pack_bf16x2(a, b);
    float ha = __uint_as_float(h << 16), hb = __uint_as_float(h & 0xFFFF0000u);
    l = pack_bf16x2(a - ha, b - hb);
}

// FMA-pipe-only sigmoid. abs err ~1.5e-5, zero MUFU.
__device__ __forceinline__ float sig_fma(float x) {
    float ax = fminf(fabsf(x), 20.0f);
    float y = -1.44269504f * ax;
    float t = y + 12582912.0f;
    int n = __float_as_int(t) - 0x4B400000;
    float f = y - (t - 12582912.0f);
    float p = 1.33335581e-3f;
    p = fmaf(p, f, 9.61812910e-3f);
    p = fmaf(p, f, 5.55041086e-2f);
    p = fmaf(p, f, 2.40226507e-1f);
    p = fmaf(p, f, 6.93147181e-1f);
    p = fmaf(p, f, 1.0f);
    float E = __int_as_float(__float_as_int(p) + (n << 23));  // e^{-ax}
    float w = 1.0f + E;
    float r = __int_as_float(0x7EF127EAu - __float_as_int(w));
    r = r * (2.0f - w * r);
    r = r * (2.0f - w * r);
    return x >= 0.0f ? r : 1.0f - r;
}

// ---------------------------------------------------------------------------
// K0: split Mr into bf16 hi/lo.
// ---------------------------------------------------------------------------
__global__ void mrsplit_kernel(const float* __restrict__ Mr) {
    size_t i = ((size_t)blockIdx.x * 256 + threadIdx.x) * 4;
    float4 v = *reinterpret_cast<const float4*>(Mr + i);
    uint32_t h0, l0, h1, l1;
    split2(v.x, v.y, h0, l0);
    split2(v.z, v.w, h1, l1);
    *reinterpret_cast<uint2*>(&g_Mrhi[i]) = make_uint2(h0, h1);
    *reinterpret_cast<uint2*>(&g_Mrlo[i]) = make_uint2(l0, l1);
}

// ---------------------------------------------------------------------------
// K1: fused projections + input split. One warp per row.
// ---------------------------------------------------------------------------
__global__ void conv_proj_kernel(const float* __restrict__ arg1,
                                 const float* __restrict__ arg2,
                                 const float* __restrict__ Wg,
                                 const float* __restrict__ V) {
    int w = (blockIdx.x * blockDim.x + threadIdx.x) >> 5;
    int lane = threadIdx.x & 31;
    bool first = (w < Bb * Ll);
    const float* src = first ? arg1 : arg2;
    int row = first ? w : w - Bb * Ll;
    int woff = first ? 0 : Dd;
    __nv_bfloat16* dh = first ? g_A1hi : g_B2hi;
    __nv_bfloat16* dl = first ? g_A1lo : g_B2lo;

    float aw[8] = {0,0,0,0,0,0,0,0}, av[8] = {0,0,0,0,0,0,0,0};
    const float* srow = src + (size_t)row * Dd;
#pragma unroll
    for (int q = 0; q < 4; q++) {
        int d0 = (q * 32 + lane) * 4;
        float4 x = *reinterpret_cast<const float4*>(srow + d0);
        uint32_t h0, l0, h1, l1;
        split2(x.x, x.y, h0, l0);
        split2(x.z, x.w, h1, l1);
        *reinterpret_cast<uint2*>(&dh[(size_t)row * Dd + d0]) = make_uint2(h0, h1);
        *reinterpret_cast<uint2*>(&dl[(size_t)row * Dd + d0]) = make_uint2(l0, l1);
        float xs[4] = {x.x, x.y, x.z, x.w};
#pragma unroll
        for (int e = 0; e < 4; e++) {
            int d = d0 + e;
            const float4* wp = reinterpret_cast<const float4*>(Wg + (size_t)(woff + d) * Ss);
            const float4* vp = reinterpret_cast<const float4*>(V  + (size_t)(woff + d) * Ss);
            float4 w0 = wp[0], w1 = wp[1], v0 = vp[0], v1 = vp[1];
            float xv = xs[e];
            aw[0] += xv*w0.x; aw[1] += xv*w0.y; aw[2] += xv*w0.z; aw[3] += xv*w0.w;
            aw[4] += xv*w1.x; aw[5] += xv*w1.y; aw[6] += xv*w1.z; aw[7] += xv*w1.w;
            av[0] += xv*v0.x; av[1] += xv*v0.y; av[2] += xv*v0.z; av[3] += xv*v0.w;
            av[4] += xv*v1.x; av[5] += xv*v1.y; av[6] += xv*v1.z; av[7] += xv*v1.w;
        }
    }
#pragma unroll
    for (int s = 0; s < 8; s++)
#pragma unroll
        for (int o = 16; o > 0; o >>= 1) {
            aw[s] += __shfl_xor_sync(0xffffffffu, aw[s], o);
            av[s] += __shfl_xor_sync(0xffffffffu, av[s], o);
        }
    if (lane == 0) {
        if (first) {
#pragma unroll
            for (int s = 0; s < 8; s++) {
                g_P1[(size_t)row * Ss + s] = aw[s];
                g_Q1[(size_t)row * Ss + s] = av[s];
            }
        } else {
            int bbv = row >> 9, j = row & 511;
#pragma unroll
            for (int s = 0; s < 8; s++) {
                g_P2t[((size_t)bbv * Ss + s) * Ll + j] = aw[s];
                g_Q2t[((size_t)bbv * Ss + s) * Ll + j] = av[s];
            }
        }
    }
}

// ---------------------------------------------------------------------------
// K2: A2[b,k][j,d] = arg2[b] @ Mr[k]^T, 3-pass bf16 via pre-split inputs.
// CTA 128x128, K-chunk 64, 3-stage cp.async, warp tile 64m x 32n (2x4 warps).
// Rows padded to 144B (conflict-free LDSM, cp.async 16B).
// ---------------------------------------------------------------------------
#define S1_OP   18432                 // 128 rows * 144B
#define S1_BUF  (4 * S1_OP)           // Ahi|Alo|Bhi|Blo = 73728
#define S1_SMEM (3 * S1_BUF)          // 221184

__global__ __launch_bounds__(256, 1) void gemm1_kernel() {
    extern __shared__ char smem[];
    uint32_t sb = smem_u32(smem);
    int t = threadIdx.x, lane = t & 31, wid = t >> 5;
    int bz = blockIdx.z, bbv = bz >> 3, kk = bz & 7;
    int j0 = blockIdx.y * 128, d0 = blockIdx.x * 128;
    int wm = wid & 1, wn = wid >> 1;

    const __nv_bfloat16* srcA[2] = {g_B2hi + ((size_t)bbv * Ll + j0) * Dd,
                                    g_B2lo + ((size_t)bbv * Ll + j0) * Dd};
    const __nv_bfloat16* srcB[2] = {g_Mrhi + ((size_t)kk * Dd + d0) * Dd,
                                    g_Mrlo + ((size_t)kk * Dd + d0) * Dd};

    auto issue = [&](int c) {
        uint32_t dstb = sb + (c % 3) * S1_BUF;
        int e0 = c * 64;
#pragma unroll
        for (int i = 0; i < 16; i++) {
            int op = i >> 2;                     // 0:Ahi 1:Alo 2:Bhi 3:Blo
            int rem = (i & 3) * 256 + t;
            int r = rem >> 3, seg = rem & 7;
            const __nv_bfloat16* s = (op < 2 ? srcA[op] : srcB[op - 2])
                                     + (size_t)r * Dd + e0 + seg * 8;
            CP16(dstb + op * S1_OP + r * 144 + seg * 16, s);
        }
        CPCOMMIT();
    };

    float acc[4][4][4];
#pragma unroll
    for (int mt = 0; mt < 4; mt++)
#pragma unroll
        for (int n8 = 0; n8 < 4; n8++)
#pragma unroll
            for (int q = 0; q < 4; q++) acc[mt][n8][q] = 0.f;

    issue(0); issue(1);
#pragma unroll 1
    for (int c = 0; c < 8; c++) {
        if (c < 7) CPWAIT1(); else CPWAIT0();
        __syncthreads();
        if (c < 6) issue(c + 2);
        uint32_t bufb = sb + (c % 3) * S1_BUF;
#pragma unroll
        for (int k16 = 0; k16 < 4; k16++) {
            uint32_t kseg = (uint32_t)((k16 * 2 + (lane >> 4)) * 16);
            uint32_t ahi[4][4], alo[4][4], bhi[2][4], blo[2][4];
#pragma unroll
            for (int mt = 0; mt < 4; mt++) {
                uint32_t aoff = (uint32_t)((wm * 64 + mt * 16 + (lane & 15)) * 144) + kseg;
                ldsm4(ahi[mt], bufb + aoff);
                ldsm4(alo[mt], bufb + S1_OP + aoff);
            }
#pragma unroll
            for (int nt2 = 0; nt2 < 2; nt2++) {
                uint32_t boff = (uint32_t)((wn * 32 + nt2 * 16 + (lane & 15)) * 144) + kseg;
                ldsm4(bhi[nt2], bufb + 2 * S1_OP + boff);
                ldsm4(blo[nt2], bufb + 3 * S1_OP + boff);
            }
#pragma unroll
            for (int mt = 0; mt < 4; mt++)
#pragma unroll
                for (int n8 = 0; n8 < 4; n8++) {
                    uint32_t bh[2] = {bhi[n8 >> 1][n8 & 1], bhi[n8 >> 1][(n8 & 1) + 2]};
                    uint32_t bl[2] = {blo[n8 >> 1][n8 & 1], blo[n8 >> 1][(n8 & 1) + 2]};
                    mma_bf16(acc[mt][n8], ahi[mt], bh);
                    mma_bf16(acc[mt][n8], ahi[mt], bl);
                    mma_bf16(acc[mt][n8], alo[mt], bh);
                }
        }
        __syncthreads();
    }

    // Drain: split fp32 acc -> bf16 hi/lo to gmem
    size_t plane = (size_t)bz * Ll * Dd;
#pragma unroll
    for (int mt = 0; mt < 4; mt++) {
        int jr = j0 + wm * 64 + mt * 16 + (lane >> 2);
#pragma unroll
        for (int n8 = 0; n8 < 4; n8++) {
            int dc = d0 + wn * 32 + n8 * 8 + (lane & 3) * 2;
            size_t x0 = plane + (size_t)jr * Dd + dc;
            size_t x1 = x0 + (size_t)8 * Dd;
            uint32_t h, l;
            split2(acc[mt][n8][0], acc[mt][n8][1], h, l);
            *reinterpret_cast<uint32_t*>(&g_A2hi[x0]) = h;
            *reinterpret_cast<uint32_t*>(&g_A2lo[x0]) = l;
            split2(acc[mt][n8][2], acc[mt][n8][3], h, l);
            *reinterpret_cast<uint32_t*>(&g_A2hi[x1]) = h;
            *reinterpret_cast<uint32_t*>(&g_A2lo[x1]) = l;
        }
    }
}

// ---------------------------------------------------------------------------
// K3: bi = arg1 @ A2^T for 8 planes + fused gated epilogue.
// CTA 64i x 64j; arg1 tile (pre-split) resident via one cp.async group;
// A2 streamed with 3-stage cp.async, K-chunk 64. Warp tile 16i x 32j (4x2).
// ---------------------------------------------------------------------------
#define S2_AOP  66560                 // 64 rows * 1040B
#define S2_BOP  9216                  // 64 rows * 144B
#define S2_BBUF (2 * S2_BOP)          // hi|lo = 18432
#define S2_BOFF (2 * S2_AOP)          // 133120
#define S2_SMEM (S2_BOFF + 3 * S2_BBUF)  // 188416

__global__ __launch_bounds__(256, 1) void gemm2_kernel(const float* __restrict__ Bg,
                                                       const float* __restrict__ bvec,
                                                       const float* __restrict__ U,
                                                       float* __restrict__ out) {
    extern __shared__ char smem[];
    uint32_t sb = smem_u32(smem);
    int t = threadIdx.x, lane = t & 31, wid = t >> 5;
    int bbv = blockIdx.z, i0 = blockIdx.y * 64, j0 = blockIdx.x * 64;
    int wi = wid & 3, wj = wid >> 2;

    // Resident A (arg1 split): one cp.async group
    {
        const __nv_bfloat16* sA[2] = {g_A1hi + ((size_t)bbv * Ll + i0) * Dd,
                                      g_A1lo + ((size_t)bbv * Ll + i0) * Dd};
#pragma unroll
        for (int i = 0; i < 32; i++) {
            int var = i >> 4;
            int rem = (i & 15) * 256 + t;
            int r = rem >> 6, seg = rem & 63;
            CP16(sb + var * S2_AOP + r * 1040 + seg * 16,
                 sA[var] + (size_t)r * Dd + seg * 8);
        }
        CPCOMMIT();
    }

    auto issueB = [&](int m) {
        int k = m >> 3, c = m & 7;
        uint32_t dstb = sb + S2_BOFF + (m % 3) * S2_BBUF;
        size_t srow = ((size_t)(bbv * 8 + k) * Ll + j0) * Dd + c * 64;
#pragma unroll
        for (int i = 0; i < 4; i++) {
            int var = i >> 1;
            int rem = (i & 1) * 256 + t;
            int r = rem >> 3, seg = rem & 7;
            const __nv_bfloat16* s = (var ? g_A2lo : g_A2hi) + srow + (size_t)r * Dd + seg * 8;
            CP16(dstb + var * S2_BOP + r * 144 + seg * 16, s);
        }
        CPCOMMIT();
    };
    issueB(0); issueB(1);

    float bU = 0.f;
#pragma unroll
    for (int s = 0; s < 8; s++) bU += bvec[s] * U[s];
    float sc[4][2][2];
#pragma unroll
    for (int nt = 0; nt < 4; nt++)
#pragma unroll
        for (int p = 0; p < 2; p++) { sc[nt][p][0] = bU; sc[nt][p][1] = bU; }

    int iL = i0 + wi * 16 + (lane >> 2);
    int iH = iL + 8;

#pragma unroll 1
    for (int k = 0; k < 8; k++) {
        float acc[4][4];
#pragma unroll
        for (int n8 = 0; n8 < 4; n8++)
#pragma unroll
            for (int q = 0; q < 4; q++) acc[n8][q] = 0.f;

#pragma unroll 1
        for (int c = 0; c < 8; c++) {
            int m = k * 8 + c;
            if (m < 63) CPWAIT1(); else CPWAIT0();
            __syncthreads();
            if (m < 62) issueB(m + 2);
            uint32_t bufb = sb + S2_BOFF + (m % 3) * S2_BBUF;
#pragma unroll
            for (int k16 = 0; k16 < 4; k16++) {
                uint32_t ahi[4], alo[4], bhi[2][4], blo[2][4];
                uint32_t aoff = (uint32_t)((wi * 16 + (lane & 15)) * 1040 +
                                           (c * 8 + k16 * 2 + (lane >> 4)) * 16);
                ldsm4(ahi, sb + aoff);
                ldsm4(alo, sb + S2_AOP + aoff);
                uint32_t kseg = (uint32_t)((k16 * 2 + (lane >> 4)) * 16);
#pragma unroll
                for (int nt2 = 0; nt2 < 2; nt2++) {
                    uint32_t boff = (uint32_t)((wj * 32 + nt2 * 16 + (lane & 15)) * 144) + kseg;
                    ldsm4(bhi[nt2], bufb + boff);
                    ldsm4(blo[nt2], bufb + S2_BOP + boff);
                }
#pragma unroll
                for (int n8 = 0; n8 < 4; n8++) {
                    uint32_t bh[2] = {bhi[n8 >> 1][n8 & 1], bhi[n8 >> 1][(n8 & 1) + 2]};
                    uint32_t bl[2] = {blo[n8 >> 1][n8 & 1], blo[n8 >> 1][(n8 & 1) + 2]};
                    mma_bf16(acc[n8], ahi, bh);
                    mma_bf16(acc[n8], ahi, bl);
                    mma_bf16(acc[n8], alo, bh);
                }
            }
            __syncthreads();
        }
        // Fused epilogue for plane k
        float BgK = Bg[k], Uk = U[k];
        float p1L = g_P1[((size_t)bbv * Ll + iL) * Ss + k] + BgK;
        float p1H = g_P1[((size_t)bbv * Ll + iH) * Ss + k] + BgK;
        float q1L = g_Q1[((size_t)bbv * Ll + iL) * Ss + k];
        float q1H = g_Q1[((size_t)bbv * Ll + iH) * Ss + k];
        const float* p2b = g_P2t + ((size_t)(bbv * 8 + k)) * Ll + j0 + wj * 32;
        const float* q2b = g_Q2t + ((size_t)(bbv * 8 + k)) * Ll + j0 + wj * 32;
#pragma unroll
        for (int nt = 0; nt < 4; nt++)
#pragma unroll
            for (int e = 0; e < 2; e++) {
                int jc = nt * 8 + (lane & 3) * 2 + e;
                float p2 = p2b[jc], q2 = q2b[jc];
                float gL = sig_fma(p1L + p2), sL = sig_fma(q1L + q2);
                float gH = sig_fma(p1H + p2), sH = sig_fma(q1H + q2);
                sc[nt][0][e] += Uk * fmaf(acc[nt][e] - sL, gL, sL);
                sc[nt][1][e] += Uk * fmaf(acc[nt][2 + e] - sH, gH, sH);
            }
    }

    // Final sigmoid + store
#pragma unroll
    for (int nt = 0; nt < 4; nt++) {
        int jc = j0 + wj * 32 + nt * 8 + (lane & 3) * 2;
        float2 v0 = make_float2(sig_fma(sc[nt][0][0]), sig_fma(sc[nt][0][1]));
        float2 v1 = make_float2(sig_fma(sc[nt][1][0]), sig_fma(sc[nt][1][1]));
        *reinterpret_cast<float2*>(&out[((size_t)bbv * Ll + iL) * Ll + jc]) = v0;
        *reinterpret_cast<float2*>(&out[((size_t)bbv * Ll + iH) * Ll + jc]) = v1;
    }
}

// ---------------------------------------------------------------------------
extern "C" void kernel_launch(void* const* d_in, const int* in_sizes, int n_in,
                              void* d_out, int out_size) {
    const float* arg1 = (const float*)d_in[0];
    const float* arg2 = (const float*)d_in[1];
    const float* Wg   = (const float*)d_in[2];
    const float* Bg   = (const float*)d_in[3];
    const float* Mr   = (const float*)d_in[4];
    const float* V    = (const float*)d_in[5];
    const float* bvec = (const float*)d_in[6];
    const float* U    = (const float*)d_in[7];
    float* out = (float*)d_out;

    cudaFuncSetAttribute(gemm1_kernel, cudaFuncAttributeMaxDynamicSharedMemorySize, S1_SMEM);
    cudaFuncSetAttribute(gemm2_kernel, cudaFuncAttributeMaxDynamicSharedMemorySize, S2_SMEM);

    mrsplit_kernel<<<(Ss * Dd * Dd) / 1024, 256>>>(Mr);
    conv_proj_kernel<<<(2 * Bb * Ll) / 8, 256>>>(arg1, arg2, Wg, V);

    dim3 g1(Dd / 128, Ll / 128, Bb * Ss);
    gemm1_kernel<<<g1, 256, S1_SMEM>>>();

    dim3 g2(Ll / 64, Ll / 64, Bb);
    gemm2_kernel<<<g2, 256, S2_SMEM>>>(Bg, bvec, U, out);
}

// round 7
// speedup vs baseline: 1.0740x; 1.0740x over previous
#include <cuda_runtime.h>
#include <cuda_bf16.h>
#include <cstdint>

#define Bb 32
#define Ll 512
#define Dd 512
#define Ss 8

// ---------------------------------------------------------------------------
// Device-global scratch
// ---------------------------------------------------------------------------
__device__ __nv_bfloat16 g_A2hi[(size_t)Bb * Ss * Ll * Dd];
__device__ __nv_bfloat16 g_A2lo[(size_t)Bb * Ss * Ll * Dd];
__device__ __nv_bfloat16 g_A1hi[(size_t)Bb * Ll * Dd];
__device__ __nv_bfloat16 g_A1lo[(size_t)Bb * Ll * Dd];
__device__ __nv_bfloat16 g_B2hi[(size_t)Bb * Ll * Dd];
__device__ __nv_bfloat16 g_B2lo[(size_t)Bb * Ll * Dd];
__device__ __nv_bfloat16 g_Mrhi[(size_t)Ss * Dd * Dd];
__device__ __nv_bfloat16 g_Mrlo[(size_t)Ss * Dd * Dd];
__device__ float g_P1[Bb * Ll * Ss];
__device__ float g_Q1[Bb * Ll * Ss];
__device__ float g_P2t[Bb * Ss * Ll];
__device__ float g_Q2t[Bb * Ss * Ll];

// ---------------------------------------------------------------------------
// Helpers
// ---------------------------------------------------------------------------
__device__ __forceinline__ uint32_t smem_u32(const void* p) {
    uint32_t a;
    asm("{ .reg .u64 t; cvta.to.shared.u64 t, %1; cvt.u32.u64 %0, t; }"
        : "=r"(a) : "l"(p));
    return a;
}
__device__ __forceinline__ void ldsm4(uint32_t* r, uint32_t a) {
    asm volatile("ldmatrix.sync.aligned.m8n8.x4.shared.b16 {%0,%1,%2,%3}, [%4];"
                 : "=r"(r[0]), "=r"(r[1]), "=r"(r[2]), "=r"(r[3]) : "r"(a) : "memory");
}
__device__ __forceinline__ void mma_bf16(float* c, const uint32_t* a, const uint32_t* b) {
    asm volatile("mma.sync.aligned.m16n8k16.row.col.f32.bf16.bf16.f32 "
                 "{%0,%1,%2,%3}, {%4,%5,%6,%7}, {%8,%9}, {%0,%1,%2,%3};"
                 : "+f"(c[0]), "+f"(c[1]), "+f"(c[2]), "+f"(c[3])
                 : "r"(a[0]), "r"(a[1]), "r"(a[2]), "r"(a[3]), "r"(b[0]), "r"(b[1]));
}
#define CP16(dst, src) \
    asm volatile("cp.async.cg.shared.global [%0], [%1], 16;" :: "r"(dst), "l"(src) : "memory")
#define CPCOMMIT() asm volatile("cp.async.commit_group;" ::: "memory")
#define CPWAIT1() asm volatile("cp.async.wait_group 1;" ::: "memory")
#define CPWAIT0() asm volatile("cp.async.wait_group 0;" ::: "memory")

__device__ __forceinline__ uint32_t pack_bf16x2(float a, float b) {
    uint32_t h;
    asm("cvt.rn.bf16x2.f32 %0, %1, %2;" : "=r"(h) : "f"(b), "f"(a));
    return h;
}
__device__ __forceinline__ void split2(float a, float b, uint32_t& h, uint32_t& l) {
    h = pack_bf16x2(a, b);
    float ha = __uint_as_float(h << 16), hb = __uint_as_float(h & 0xFFFF0000u);
    l = pack_bf16x2(a - ha, b - hb);
}

// FMA-pipe-only sigmoid, abs err ~1.5e-5
__device__ __forceinline__ float sig_fma(float x) {
    float ax = fminf(fabsf(x), 20.0f);
    float y = -1.44269504f * ax;
    float t = y + 12582912.0f;
    int n = __float_as_int(t) - 0x4B400000;
    float f = y - (t - 12582912.0f);
    float p = 1.33335581e-3f;
    p = fmaf(p, f, 9.61812910e-3f);
    p = fmaf(p, f, 5.55041086e-2f);
    p = fmaf(p, f, 2.40226507e-1f);
    p = fmaf(p, f, 6.93147181e-1f);
    p = fmaf(p, f, 1.0f);
    float E = __int_as_float(__float_as_int(p) + (n << 23));
    float w = 1.0f + E;
    float r = __int_as_float(0x7EF127EAu - __float_as_int(w));
    r = r * (2.0f - w * r);
    r = r * (2.0f - w * r);
    return x >= 0.0f ? r : 1.0f - r;
}

// ---------------------------------------------------------------------------
// K0: split Mr into bf16 hi/lo
// ---------------------------------------------------------------------------
__global__ void mrsplit_kernel(const float* __restrict__ Mr) {
    size_t i = ((size_t)blockIdx.x * 256 + threadIdx.x) * 4;
    float4 v = *reinterpret_cast<const float4*>(Mr + i);
    uint32_t h0, l0, h1, l1;
    split2(v.x, v.y, h0, l0);
    split2(v.z, v.w, h1, l1);
    *reinterpret_cast<uint2*>(&g_Mrhi[i]) = make_uint2(h0, h1);
    *reinterpret_cast<uint2*>(&g_Mrlo[i]) = make_uint2(l0, l1);
}

// ---------------------------------------------------------------------------
// K1: fused projections + input split. One warp per row.
// ---------------------------------------------------------------------------
__global__ void conv_proj_kernel(const float* __restrict__ arg1,
                                 const float* __restrict__ arg2,
                                 const float* __restrict__ Wg,
                                 const float* __restrict__ V) {
    int w = (blockIdx.x * blockDim.x + threadIdx.x) >> 5;
    int lane = threadIdx.x & 31;
    bool first = (w < Bb * Ll);
    const float* src = first ? arg1 : arg2;
    int row = first ? w : w - Bb * Ll;
    int woff = first ? 0 : Dd;
    __nv_bfloat16* dh = first ? g_A1hi : g_B2hi;
    __nv_bfloat16* dl = first ? g_A1lo : g_B2lo;

    float aw[8] = {0,0,0,0,0,0,0,0}, av[8] = {0,0,0,0,0,0,0,0};
    const float* srow = src + (size_t)row * Dd;
#pragma unroll
    for (int q = 0; q < 4; q++) {
        int d0 = (q * 32 + lane) * 4;
        float4 x = *reinterpret_cast<const float4*>(srow + d0);
        uint32_t h0, l0, h1, l1;
        split2(x.x, x.y, h0, l0);
        split2(x.z, x.w, h1, l1);
        *reinterpret_cast<uint2*>(&dh[(size_t)row * Dd + d0]) = make_uint2(h0, h1);
        *reinterpret_cast<uint2*>(&dl[(size_t)row * Dd + d0]) = make_uint2(l0, l1);
        float xs[4] = {x.x, x.y, x.z, x.w};
#pragma unroll
        for (int e = 0; e < 4; e++) {
            int d = d0 + e;
            const float4* wp = reinterpret_cast<const float4*>(Wg + (size_t)(woff + d) * Ss);
            const float4* vp = reinterpret_cast<const float4*>(V  + (size_t)(woff + d) * Ss);
            float4 w0 = wp[0], w1 = wp[1], v0 = vp[0], v1 = vp[1];
            float xv = xs[e];
            aw[0] += xv*w0.x; aw[1] += xv*w0.y; aw[2] += xv*w0.z; aw[3] += xv*w0.w;
            aw[4] += xv*w1.x; aw[5] += xv*w1.y; aw[6] += xv*w1.z; aw[7] += xv*w1.w;
            av[0] += xv*v0.x; av[1] += xv*v0.y; av[2] += xv*v0.z; av[3] += xv*v0.w;
            av[4] += xv*v1.x; av[5] += xv*v1.y; av[6] += xv*v1.z; av[7] += xv*v1.w;
        }
    }
#pragma unroll
    for (int s = 0; s < 8; s++)
#pragma unroll
        for (int o = 16; o > 0; o >>= 1) {
            aw[s] += __shfl_xor_sync(0xffffffffu, aw[s], o);
            av[s] += __shfl_xor_sync(0xffffffffu, av[s], o);
        }
    if (lane == 0) {
        if (first) {
#pragma unroll
            for (int s = 0; s < 8; s++) {
                g_P1[(size_t)row * Ss + s] = aw[s];
                g_Q1[(size_t)row * Ss + s] = av[s];
            }
        } else {
            int bbv = row >> 9, j = row & 511;
#pragma unroll
            for (int s = 0; s < 8; s++) {
                g_P2t[((size_t)bbv * Ss + s) * Ll + j] = aw[s];
                g_Q2t[((size_t)bbv * Ss + s) * Ll + j] = av[s];
            }
        }
    }
}

// ---------------------------------------------------------------------------
// K2: A2 = arg2 @ Mr^T, 3-pass. CTA 128x128, 512 thr (16 warps, 32m x 32n),
// K-chunk 64, 3-stage cp.async. Rows padded 144B.
// ---------------------------------------------------------------------------
#define S1_OP   18432
#define S1_BUF  (4 * S1_OP)
#define S1_SMEM (3 * S1_BUF)

__global__ __launch_bounds__(512, 1) void gemm1_kernel() {
    extern __shared__ char smem[];
    uint32_t sb = smem_u32(smem);
    int t = threadIdx.x, lane = t & 31, wid = t >> 5;
    int bz = blockIdx.z, bbv = bz >> 3, kk = bz & 7;
    int j0 = blockIdx.y * 128, d0 = blockIdx.x * 128;
    int wm = wid & 3, wn = wid >> 2;

    const __nv_bfloat16* srcOp[4] = {
        g_B2hi + ((size_t)bbv * Ll + j0) * Dd,
        g_B2lo + ((size_t)bbv * Ll + j0) * Dd,
        g_Mrhi + ((size_t)kk * Dd + d0) * Dd,
        g_Mrlo + ((size_t)kk * Dd + d0) * Dd};

    // per-thread load offsets (two slots per operand)
    int r0 = t >> 3, s0 = t & 7;
    int r1 = (512 + t) >> 3, s1 = t & 7;
    size_t gOff0 = (size_t)r0 * Dd + s0 * 8;
    size_t gOff1 = (size_t)r1 * Dd + s1 * 8;
    uint32_t sOff0 = (uint32_t)(r0 * 144 + s0 * 16);
    uint32_t sOff1 = (uint32_t)(r1 * 144 + s1 * 16);

    auto issue = [&](int c) {
        uint32_t dstb = sb + (c % 3) * S1_BUF;
        int e0 = c * 64;
#pragma unroll
        for (int op = 0; op < 4; op++) {
            CP16(dstb + op * S1_OP + sOff0, srcOp[op] + gOff0 + e0);
            CP16(dstb + op * S1_OP + sOff1, srcOp[op] + gOff1 + e0);
        }
        CPCOMMIT();
    };

    // per-warp ldsm bases
    uint32_t aBase[2], bBase[2];
#pragma unroll
    for (int mt = 0; mt < 2; mt++)
        aBase[mt] = (uint32_t)((wm * 32 + mt * 16 + (lane & 15)) * 144 + (lane >> 4) * 16);
#pragma unroll
    for (int nt = 0; nt < 2; nt++)
        bBase[nt] = (uint32_t)((wn * 32 + nt * 16 + (lane & 15)) * 144 + (lane >> 4) * 16);

    float acc[2][4][4];
#pragma unroll
    for (int mt = 0; mt < 2; mt++)
#pragma unroll
        for (int n8 = 0; n8 < 4; n8++)
#pragma unroll
            for (int q = 0; q < 4; q++) acc[mt][n8][q] = 0.f;

    issue(0); issue(1);
#pragma unroll 1
    for (int c = 0; c < 8; c++) {
        if (c < 7) CPWAIT1(); else CPWAIT0();
        __syncthreads();
        if (c < 6) issue(c + 2);
        uint32_t bufb = sb + (c % 3) * S1_BUF;
#pragma unroll
        for (int k16 = 0; k16 < 4; k16++) {
            uint32_t kadd = (uint32_t)(k16 * 32);
            uint32_t ahi[2][4], alo[2][4], bhi[2][4], blo[2][4];
#pragma unroll
            for (int mt = 0; mt < 2; mt++) {
                ldsm4(ahi[mt], bufb + aBase[mt] + kadd);
                ldsm4(alo[mt], bufb + S1_OP + aBase[mt] + kadd);
            }
#pragma unroll
            for (int nt = 0; nt < 2; nt++) {
                ldsm4(bhi[nt], bufb + 2 * S1_OP + bBase[nt] + kadd);
                ldsm4(blo[nt], bufb + 3 * S1_OP + bBase[nt] + kadd);
            }
#pragma unroll
            for (int mt = 0; mt < 2; mt++)
#pragma unroll
                for (int n8 = 0; n8 < 4; n8++) {
                    uint32_t bh[2] = {bhi[n8 >> 1][n8 & 1], bhi[n8 >> 1][(n8 & 1) + 2]};
                    uint32_t bl[2] = {blo[n8 >> 1][n8 & 1], blo[n8 >> 1][(n8 & 1) + 2]};
                    mma_bf16(acc[mt][n8], ahi[mt], bh);
                    mma_bf16(acc[mt][n8], ahi[mt], bl);
                    mma_bf16(acc[mt][n8], alo[mt], bh);
                }
        }
        __syncthreads();
    }

    size_t plane = (size_t)bz * Ll * Dd;
#pragma unroll
    for (int mt = 0; mt < 2; mt++) {
        int jr = j0 + wm * 32 + mt * 16 + (lane >> 2);
#pragma unroll
        for (int n8 = 0; n8 < 4; n8++) {
            int dc = d0 + wn * 32 + n8 * 8 + (lane & 3) * 2;
            size_t x0 = plane + (size_t)jr * Dd + dc;
            size_t x1 = x0 + (size_t)8 * Dd;
            uint32_t h, l;
            split2(acc[mt][n8][0], acc[mt][n8][1], h, l);
            *reinterpret_cast<uint32_t*>(&g_A2hi[x0]) = h;
            *reinterpret_cast<uint32_t*>(&g_A2lo[x0]) = l;
            split2(acc[mt][n8][2], acc[mt][n8][3], h, l);
            *reinterpret_cast<uint32_t*>(&g_A2hi[x1]) = h;
            *reinterpret_cast<uint32_t*>(&g_A2lo[x1]) = l;
        }
    }
}

// ---------------------------------------------------------------------------
// K3: bi = arg1 @ A2^T (8 planes) + fused epilogue.
// CTA 64i x 128j, 512 thr (16 warps: 4i x 4j, warp tile 16i x 32j).
// A resident (133KB), B 2-stage (2 x 36.9KB). Total SMEM 207KB.
// ---------------------------------------------------------------------------
#define S2_AOP   66560                    // 64 * 1040
#define S2_BOP   18432                    // 128 * 144
#define S2_BBUF  (2 * S2_BOP)             // 36864
#define S2_BOFF  (2 * S2_AOP)             // 133120
#define S2_SMEM  (S2_BOFF + 2 * S2_BBUF)  // 206848

__global__ __launch_bounds__(512, 1) void gemm2_kernel(const float* __restrict__ Bg,
                                                       const float* __restrict__ bvec,
                                                       const float* __restrict__ U,
                                                       float* __restrict__ out) {
    extern __shared__ char smem[];
    uint32_t sb = smem_u32(smem);
    int t = threadIdx.x, lane = t & 31, wid = t >> 5;
    int bbv = blockIdx.z, i0 = blockIdx.y * 64, j0 = blockIdx.x * 128;
    int wi = wid & 3, wj = wid >> 2;

    // Resident A (arg1 split): one cp.async group (16 CP16 / thread)
    {
        const __nv_bfloat16* sA[2] = {g_A1hi + ((size_t)bbv * Ll + i0) * Dd,
                                      g_A1lo + ((size_t)bbv * Ll + i0) * Dd};
#pragma unroll
        for (int i = 0; i < 16; i++) {
            int var = i >> 3;
            int rem = (i & 7) * 512 + t;
            int r = rem >> 6, seg = rem & 63;
            CP16(sb + var * S2_AOP + r * 1040 + seg * 16,
                 sA[var] + (size_t)r * Dd + seg * 8);
        }
        CPCOMMIT();
    }

    // per-thread B load offsets (two slots per variant)
    int rB0 = t >> 3, sB0 = t & 7;
    int rB1 = (512 + t) >> 3;
    size_t gB0 = (size_t)rB0 * Dd + sB0 * 8;
    size_t gB1 = (size_t)rB1 * Dd + sB0 * 8;
    uint32_t sB0o = (uint32_t)(rB0 * 144 + sB0 * 16);
    uint32_t sB1o = (uint32_t)(rB1 * 144 + sB0 * 16);
    const __nv_bfloat16* bHi = g_A2hi + ((size_t)bbv * 8 * Ll + j0) * Dd;
    const __nv_bfloat16* bLo = g_A2lo + ((size_t)bbv * 8 * Ll + j0) * Dd;

    auto issueB = [&](int m) {
        int k = m >> 3, c = m & 7;
        uint32_t dstb = sb + S2_BOFF + (m & 1) * S2_BBUF;
        size_t base = (size_t)k * Ll * Dd + c * 64;
        CP16(dstb + sB0o, bHi + base + gB0);
        CP16(dstb + sB1o, bHi + base + gB1);
        CP16(dstb + S2_BOP + sB0o, bLo + base + gB0);
        CP16(dstb + S2_BOP + sB1o, bLo + base + gB1);
        CPCOMMIT();
    };
    issueB(0);

    // per-warp ldsm bases
    uint32_t aBase = (uint32_t)((wi * 16 + (lane & 15)) * 1040 + (lane >> 4) * 16);
    uint32_t bBase[2];
#pragma unroll
    for (int nt = 0; nt < 2; nt++)
        bBase[nt] = (uint32_t)((wj * 32 + nt * 16 + (lane & 15)) * 144 + (lane >> 4) * 16);

    float bU = 0.f;
#pragma unroll
    for (int s = 0; s < 8; s++) bU += bvec[s] * U[s];
    float sc[4][2][2];
#pragma unroll
    for (int nt = 0; nt < 4; nt++)
#pragma unroll
        for (int p = 0; p < 2; p++) { sc[nt][p][0] = bU; sc[nt][p][1] = bU; }

    int iL = i0 + wi * 16 + (lane >> 2);
    int iH = iL + 8;

#pragma unroll 1
    for (int k = 0; k < 8; k++) {
        float acc[4][4];
#pragma unroll
        for (int n8 = 0; n8 < 4; n8++)
#pragma unroll
            for (int q = 0; q < 4; q++) acc[n8][q] = 0.f;

#pragma unroll 1
        for (int c = 0; c < 8; c++) {
            int m = k * 8 + c;
            if (m < 63) { issueB(m + 1); CPWAIT1(); } else CPWAIT0();
            __syncthreads();
            uint32_t bufb = sb + S2_BOFF + (m & 1) * S2_BBUF;
#pragma unroll
            for (int k16 = 0; k16 < 4; k16++) {
                uint32_t ahi[4], alo[4], bhi[2][4], blo[2][4];
                uint32_t aoff = aBase + (uint32_t)(c * 128 + k16 * 32);
                ldsm4(ahi, sb + aoff);
                ldsm4(alo, sb + S2_AOP + aoff);
                uint32_t kadd = (uint32_t)(k16 * 32);
#pragma unroll
                for (int nt = 0; nt < 2; nt++) {
                    ldsm4(bhi[nt], bufb + bBase[nt] + kadd);
                    ldsm4(blo[nt], bufb + S2_BOP + bBase[nt] + kadd);
                }
#pragma unroll
                for (int n8 = 0; n8 < 4; n8++) {
                    uint32_t bh[2] = {bhi[n8 >> 1][n8 & 1], bhi[n8 >> 1][(n8 & 1) + 2]};
                    uint32_t bl[2] = {blo[n8 >> 1][n8 & 1], blo[n8 >> 1][(n8 & 1) + 2]};
                    mma_bf16(acc[n8], ahi, bh);
                    mma_bf16(acc[n8], ahi, bl);
                    mma_bf16(acc[n8], alo, bh);
                }
            }
            __syncthreads();
        }
        // Fused epilogue for plane k
        float BgK = Bg[k], Uk = U[k];
        float p1L = g_P1[((size_t)bbv * Ll + iL) * Ss + k] + BgK;
        float p1H = g_P1[((size_t)bbv * Ll + iH) * Ss + k] + BgK;
        float q1L = g_Q1[((size_t)bbv * Ll + iL) * Ss + k];
        float q1H = g_Q1[((size_t)bbv * Ll + iH) * Ss + k];
        const float* p2b = g_P2t + ((size_t)(bbv * 8 + k)) * Ll + j0 + wj * 32;
        const float* q2b = g_Q2t + ((size_t)(bbv * 8 + k)) * Ll + j0 + wj * 32;
#pragma unroll
        for (int nt = 0; nt < 4; nt++)
#pragma unroll
            for (int e = 0; e < 2; e++) {
                int jc = nt * 8 + (lane & 3) * 2 + e;
                float p2 = p2b[jc], q2 = q2b[jc];
                float gL = sig_fma(p1L + p2), sL = sig_fma(q1L + q2);
                float gH = sig_fma(p1H + p2), sH = sig_fma(q1H + q2);
                sc[nt][0][e] += Uk * fmaf(acc[nt][e] - sL, gL, sL);
                sc[nt][1][e] += Uk * fmaf(acc[nt][2 + e] - sH, gH, sH);
            }
    }

    // Final sigmoid + store
#pragma unroll
    for (int nt = 0; nt < 4; nt++) {
        int jc = j0 + wj * 32 + nt * 8 + (lane & 3) * 2;
        float2 v0 = make_float2(sig_fma(sc[nt][0][0]), sig_fma(sc[nt][0][1]));
        float2 v1 = make_float2(sig_fma(sc[nt][1][0]), sig_fma(sc[nt][1][1]));
        *reinterpret_cast<float2*>(&out[((size_t)bbv * Ll + iL) * Ll + jc]) = v0;
        *reinterpret_cast<float2*>(&out[((size_t)bbv * Ll + iH) * Ll + jc]) = v1;
    }
}

// ---------------------------------------------------------------------------
extern "C" void kernel_launch(void* const* d_in, const int* in_sizes, int n_in,
                              void* d_out, int out_size) {
    const float* arg1 = (const float*)d_in[0];
    const float* arg2 = (const float*)d_in[1];
    const float* Wg   = (const float*)d_in[2];
    const float* Bg   = (const float*)d_in[3];
    const float* Mr   = (const float*)d_in[4];
    const float* V    = (const float*)d_in[5];
    const float* bvec = (const float*)d_in[6];
    const float* U    = (const float*)d_in[7];
    float* out = (float*)d_out;

    cudaFuncSetAttribute(gemm1_kernel, cudaFuncAttributeMaxDynamicSharedMemorySize, S1_SMEM);
    cudaFuncSetAttribute(gemm2_kernel, cudaFuncAttributeMaxDynamicSharedMemorySize, S2_SMEM);

    mrsplit_kernel<<<(Ss * Dd * Dd) / 1024, 256>>>(Mr);
    conv_proj_kernel<<<(2 * Bb * Ll) / 8, 256>>>(arg1, arg2, Wg, V);

    dim3 g1(Dd / 128, Ll / 128, Bb * Ss);
    gemm1_kernel<<<g1, 512, S1_SMEM>>>();

    dim3 g2(Ll / 128, Ll / 64, Bb);
    gemm2_kernel<<<g2, 512, S2_SMEM>>>(Bg, bvec, U, out);
}